// round 2
// baseline (speedup 1.0000x reference)
#include <cuda_runtime.h>
#include <cstddef>

// ---------------- constants ----------------
#define BSZ   4
#define SEQ   256
#define DM    512
#define NH    8
#define TW    65          // window length
#define NWIN  1024        // BSZ*SEQ
#define NROWS 66560       // NWIN*TW
#define VOC   32000
#define DFFN  2048
#define DIN   1024        // ssm d_inner
#define DST   16          // ssm d_state

// ---------------- device scratch ----------------
__device__ float g_emb [BSZ*SEQ*DM];
__device__ float g_ssmv[16*BSZ*DM];
__device__ float g_hst [2*BSZ*DIN*DST];
__device__ float g_sx  [BSZ*DM];
__device__ float g_xz  [BSZ*2*DIN];
__device__ float g_dt  [BSZ*DIN];
__device__ float g_Bm  [BSZ*DST];
__device__ float g_Cm  [BSZ*DST];
__device__ float g_y   [BSZ*DIN];
__device__ float g_pwq [DM];

__device__ float g_X   [(size_t)NROWS*DM];    // residual stream
__device__ float g_XN  [(size_t)NROWS*DM];    // LN output
__device__ float g_wide[(size_t)NROWS*DFFN];  // QKV(1536)/H(2048)/KV(1024) shared
__device__ float g_O   [(size_t)NROWS*DM];    // attn out
__device__ float g_Ql  [(size_t)NWIN*DM];
__device__ float g_Ol  [(size_t)NWIN*DM];
__device__ float g_XL  [(size_t)NWIN*DM];
__device__ float g_HL  [(size_t)NWIN*DFFN];
__device__ float g_FL  [(size_t)NWIN*DM];

// ---------------- device helpers ----------------
__device__ __forceinline__ float softplusf(float x){
    return (x > 20.f) ? x : log1pf(expf(x));
}
__device__ __forceinline__ float geluf(float x){
    float x3 = x*x*x;
    return 0.5f*x*(1.f + tanhf(0.7978845608028654f*(x + 0.044715f*x3)));
}
__device__ __forceinline__ float siluf(float z){
    return z / (1.f + expf(-z));
}

// ---------------- init / embed ----------------
__global__ void init_zero_kernel(){
    int i = blockIdx.x*256 + threadIdx.x;
    if (i < 2*BSZ*DIN*DST) g_hst[i] = 0.f;
    if (i < BSZ*DM)        g_ssmv[i] = 0.f;
}

__global__ void build_emb_kernel(const int* __restrict__ ids,
                                 const float* __restrict__ table){
    int i = blockIdx.x;               // b*SEQ+t
    int id = ids[i];
    const float* src = table + (size_t)id*DM;
    float* dst = g_emb + (size_t)i*DM;
    for (int c = threadIdx.x; c < DM; c += 128) dst[c] = src[c];
}

__global__ void pwq_kernel(const float* __restrict__ wk,
                           const float* __restrict__ q){
    int d = threadIdx.x;              // 512 threads
    float s = 0.f;
    #pragma unroll
    for (int k = 0; k < 64; k++) s += wk[d*64 + k]*q[k];
    g_pwq[d] = s;
}

// ---------------- Phase A: pooling + SSM ----------------
__global__ void pool_kernel(int t, int kprev){
    int b = blockIdx.x;
    __shared__ float sc[TW];
    __shared__ float sinv;
    int tid = threadIdx.x;            // 256
    if (tid < TW){
        const float* row = nullptr;
        if (tid == 0) row = g_ssmv + ((size_t)kprev*BSZ + b)*DM;
        else {
            int tt = t - 64 + tid;
            if (tt >= 0) row = g_emb + ((size_t)b*SEQ + tt)*DM;
        }
        float s = 0.f;
        if (row) for (int d = 0; d < DM; d++) s += row[d]*g_pwq[d];
        sc[tid] = s*0.125f;
    }
    __syncthreads();
    if (tid == 0){
        float m = -1e30f;
        for (int j = 0; j < TW; j++) m = fmaxf(m, sc[j]);
        float su = 0.f;
        for (int j = 0; j < TW; j++){ float e = expf(sc[j]-m); sc[j] = e; su += e; }
        sinv = 1.f/su;
    }
    __syncthreads();
    for (int d = tid; d < DM; d += 256){
        float acc = sc[0]*g_ssmv[((size_t)kprev*BSZ + b)*DM + d];
        for (int j = 1; j < TW; j++){
            int tt = t - 64 + j;
            if (tt >= 0) acc += sc[j]*g_emb[((size_t)b*SEQ + tt)*DM + d];
        }
        g_sx[b*DM + d] = acc*sinv;
    }
}

__global__ void ssm_xz_kernel(const float* __restrict__ win){
    __shared__ float xs[DM];
    int b = blockIdx.y;
    int c = blockIdx.x*256 + threadIdx.x;       // 0..2047
    xs[threadIdx.x]       = g_sx[b*DM + threadIdx.x];
    xs[threadIdx.x + 256] = g_sx[b*DM + threadIdx.x + 256];
    __syncthreads();
    float s = 0.f;
    #pragma unroll 8
    for (int d = 0; d < DM; d++) s += xs[d]*win[(size_t)d*2048 + c];
    g_xz[b*2048 + c] = s;
}

__global__ void ssm_dt_kernel(const float* __restrict__ wdt,
                              const float* __restrict__ bdt){
    __shared__ float xs[DIN];
    int b = blockIdx.y;
    int c = blockIdx.x*256 + threadIdx.x;       // 0..1023
    for (int i = threadIdx.x; i < DIN; i += 256) xs[i] = g_xz[b*2048 + i];
    __syncthreads();
    float s = bdt[c];
    #pragma unroll 8
    for (int d = 0; d < DIN; d++) s += xs[d]*wdt[(size_t)d*DIN + c];
    g_dt[b*DIN + c] = softplusf(s);
}

__global__ void ssm_bc_kernel(const float* __restrict__ wB,
                              const float* __restrict__ wC){
    int b = blockIdx.x;
    int tid = threadIdx.x;                      // 32
    const float* w = (tid < 16) ? wB : wC;
    int s = tid & 15;
    float acc = 0.f;
    #pragma unroll 4
    for (int d = 0; d < DIN; d++) acc += g_xz[b*2048 + d]*w[d*DST + s];
    if (tid < 16) g_Bm[b*DST + s] = acc; else g_Cm[b*DST + s] = acc;
}

__global__ void ssm_hy_kernel(const float* __restrict__ Alog,
                              const float* __restrict__ Dw, int l){
    int b = blockIdx.y;
    int d = blockIdx.x*256 + threadIdx.x;
    float x1 = g_xz[b*2048 + d];
    float z  = g_xz[b*2048 + DIN + d];
    float dt = g_dt[b*DIN + d];
    float* hp = g_hst + (((size_t)l*BSZ + b)*DIN + d)*DST;
    float y = 0.f;
    #pragma unroll
    for (int s = 0; s < DST; s++){
        float Av = -expf(Alog[d*DST + s]);
        float hv = expf(dt*Av)*hp[s] + dt*g_Bm[b*DST + s]*x1;
        hp[s] = hv;
        y += hv*g_Cm[b*DST + s];
    }
    y += Dw[d]*x1;
    y *= siluf(z);
    g_y[b*DIN + d] = y;
}

__global__ void ssm_xup_kernel(const float* __restrict__ wout){
    __shared__ float ys[DIN];
    int b = blockIdx.y;
    int c = blockIdx.x*256 + threadIdx.x;       // 0..511
    for (int i = threadIdx.x; i < DIN; i += 256) ys[i] = g_y[b*DIN + i];
    __syncthreads();
    float s = 0.f;
    #pragma unroll 8
    for (int d = 0; d < DIN; d++) s += ys[d]*wout[(size_t)d*DM + c];
    g_sx[b*DM + c] += s;
}

__global__ void copy_ssm_kernel(int k){
    int i = blockIdx.x*256 + threadIdx.x;       // 0..2047
    g_ssmv[(size_t)k*BSZ*DM + i] = g_sx[i];
}

// ---------------- Phase B: batched transformer ----------------
__global__ void build_x_kernel(){
    int r = blockIdx.x;                // 0..66559
    int w = r/TW, j = r - w*TW;
    int b = w >> 8, t = w & 255;
    float* dst = g_X + (size_t)r*DM;
    const float* src = nullptr;
    if (j == 0){
        int k = (t >= 17) ? ((t-1) >> 4) : 0;
        src = g_ssmv + ((size_t)k*BSZ + b)*DM;
    } else {
        int tt = t - 64 + j;
        if (tt >= 0) src = g_emb + ((size_t)b*SEQ + tt)*DM;
    }
    for (int c = threadIdx.x; c < DM; c += 128)
        dst[c] = src ? src[c] : 0.f;
}

__global__ void ln_kernel(const float* __restrict__ in, long long ldi,
                          float* __restrict__ out, long long ldo,
                          const float* __restrict__ gw,
                          const float* __restrict__ bw){
    long long r = blockIdx.x;
    const float* x = in + r*ldi;
    int tid = threadIdx.x;             // 256
    float v0 = x[tid], v1 = x[tid + 256];
    float s = v0 + v1, q = v0*v0 + v1*v1;
    __shared__ float ss[8], sq[8];
    for (int o = 16; o; o >>= 1){
        s += __shfl_xor_sync(0xffffffffu, s, o);
        q += __shfl_xor_sync(0xffffffffu, q, o);
    }
    if ((tid & 31) == 0){ ss[tid >> 5] = s; sq[tid >> 5] = q; }
    __syncthreads();
    if (tid < 8){
        s = ss[tid]; q = sq[tid];
        for (int o = 4; o; o >>= 1){
            s += __shfl_xor_sync(0xffu, s, o);
            q += __shfl_xor_sync(0xffu, q, o);
        }
        if (tid == 0){ ss[0] = s; sq[0] = q; }
    }
    __syncthreads();
    float mu  = ss[0]*(1.f/512.f);
    float var = sq[0]*(1.f/512.f) - mu*mu;
    float inv = rsqrtf(var + 1e-5f);
    float* o = out + r*ldo;
    o[tid]       = (v0 - mu)*inv*gw[tid] + bw[tid];
    o[tid + 256] = (v1 - mu)*inv*gw[tid + 256] + bw[tid + 256];
}

// tiled SGEMM: C(MxN) = A(MxK) @ B(KxN) [+bias][gelu][+=C]
#define GBM 128
#define GBN 64
#define GBK 16
template<int ACT, bool RESID, bool HASBIAS>
__global__ __launch_bounds__(256)
void sgemm_nn(const float* __restrict__ A, long long lda,
              const float* __restrict__ B, long long ldb,
              float* __restrict__ C, long long ldc,
              const float* __restrict__ bias, int K){
    __shared__ float As[GBK][GBM];
    __shared__ float Bs[GBK][GBN];
    int bm = blockIdx.y*GBM, bn = blockIdx.x*GBN;
    int tid = threadIdx.x;
    int tx = tid & 15, ty = tid >> 4;
    float acc[8][4];
    #pragma unroll
    for (int i = 0; i < 8; i++)
        #pragma unroll
        for (int j = 0; j < 4; j++) acc[i][j] = 0.f;
    const float* Ap = A + (size_t)bm*lda;
    const float* Bp = B + bn;
    for (int k0 = 0; k0 < K; k0 += GBK){
        #pragma unroll
        for (int i = 0; i < 2; i++){
            int idx = tid + i*256;
            int m = idx >> 2, kq = (idx & 3)*4;
            float4 v = *(const float4*)(Ap + (size_t)m*lda + k0 + kq);
            As[kq+0][m] = v.x; As[kq+1][m] = v.y;
            As[kq+2][m] = v.z; As[kq+3][m] = v.w;
        }
        {
            int kk = tid >> 4, nq = (tid & 15)*4;
            float4 v = *(const float4*)(Bp + (size_t)(k0+kk)*ldb + nq);
            *(float4*)&Bs[kk][nq] = v;
        }
        __syncthreads();
        #pragma unroll
        for (int kk = 0; kk < GBK; kk++){
            float4 a0 = *(const float4*)&As[kk][ty*8];
            float4 a1 = *(const float4*)&As[kk][ty*8 + 4];
            float4 bf = *(const float4*)&Bs[kk][tx*4];
            float av[8] = {a0.x,a0.y,a0.z,a0.w,a1.x,a1.y,a1.z,a1.w};
            float bv[4] = {bf.x,bf.y,bf.z,bf.w};
            #pragma unroll
            for (int i = 0; i < 8; i++)
                #pragma unroll
                for (int j = 0; j < 4; j++) acc[i][j] += av[i]*bv[j];
        }
        __syncthreads();
    }
    #pragma unroll
    for (int i = 0; i < 8; i++){
        int row = bm + ty*8 + i;
        #pragma unroll
        for (int j = 0; j < 4; j++){
            int col = bn + tx*4 + j;
            float v = acc[i][j];
            if (HASBIAS) v += bias[col];
            if (ACT == 1) v = geluf(v);
            float* cp = C + (size_t)row*ldc + col;
            if (RESID) v += *cp;
            *cp = v;
        }
    }
}

// SGEMM-NT for logits: C(MxN) = A(MxK) @ B^T, B is (N,K) row-major
__global__ __launch_bounds__(256)
void sgemm_nt(const float* __restrict__ A, long long lda,
              const float* __restrict__ B, long long ldb,
              float* __restrict__ C, long long ldc, int K){
    __shared__ float As[GBK][GBM];
    __shared__ float Bs[GBK][GBN];
    int bm = blockIdx.y*GBM, bn = blockIdx.x*GBN;
    int tid = threadIdx.x;
    int tx = tid & 15, ty = tid >> 4;
    float acc[8][4];
    #pragma unroll
    for (int i = 0; i < 8; i++)
        #pragma unroll
        for (int j = 0; j < 4; j++) acc[i][j] = 0.f;
    const float* Ap = A + (size_t)bm*lda;
    const float* Bp = B + (size_t)bn*ldb;
    for (int k0 = 0; k0 < K; k0 += GBK){
        #pragma unroll
        for (int i = 0; i < 2; i++){
            int idx = tid + i*256;
            int m = idx >> 2, kq = (idx & 3)*4;
            float4 v = *(const float4*)(Ap + (size_t)m*lda + k0 + kq);
            As[kq+0][m] = v.x; As[kq+1][m] = v.y;
            As[kq+2][m] = v.z; As[kq+3][m] = v.w;
        }
        {
            int n = tid >> 2, kq = (tid & 3)*4;
            float4 v = *(const float4*)(Bp + (size_t)n*ldb + k0 + kq);
            Bs[kq+0][n] = v.x; Bs[kq+1][n] = v.y;
            Bs[kq+2][n] = v.z; Bs[kq+3][n] = v.w;
        }
        __syncthreads();
        #pragma unroll
        for (int kk = 0; kk < GBK; kk++){
            float4 a0 = *(const float4*)&As[kk][ty*8];
            float4 a1 = *(const float4*)&As[kk][ty*8 + 4];
            float4 bf = *(const float4*)&Bs[kk][tx*4];
            float av[8] = {a0.x,a0.y,a0.z,a0.w,a1.x,a1.y,a1.z,a1.w};
            float bv[4] = {bf.x,bf.y,bf.z,bf.w};
            #pragma unroll
            for (int i = 0; i < 8; i++)
                #pragma unroll
                for (int j = 0; j < 4; j++) acc[i][j] += av[i]*bv[j];
        }
        __syncthreads();
    }
    #pragma unroll
    for (int i = 0; i < 8; i++){
        int row = bm + ty*8 + i;
        #pragma unroll
        for (int j = 0; j < 4; j++)
            C[(size_t)row*ldc + bn + tx*4 + j] = acc[i][j];
    }
}

// full causal attention (layer 0): per (window, head) block
__global__ __launch_bounds__(256)
void attn_full_kernel(const float* __restrict__ QKV, float* __restrict__ O){
    int w = blockIdx.x, h = blockIdx.y;
    __shared__ float Ks[TW*TW];     // stride 65 (odd -> conflict-free)
    __shared__ float Vs[TW*TW];
    __shared__ float qs[8][64];
    __shared__ float ps[8][68];
    int tid = threadIdx.x;
    int lane = tid & 31, wid = tid >> 5;
    const float* base = QKV + (size_t)w*TW*1536 + h*64;
    for (int idx = tid; idx < TW*64; idx += 256){
        int j = idx >> 6, d = idx & 63;
        Ks[j*TW + d] = base[(size_t)j*1536 + 512 + d];
        Vs[j*TW + d] = base[(size_t)j*1536 + 1024 + d];
    }
    __syncthreads();
    for (int j = wid; j < TW; j += 8){
        qs[wid][lane]      = base[(size_t)j*1536 + lane];
        qs[wid][lane + 32] = base[(size_t)j*1536 + lane + 32];
        __syncwarp();
        int nk = j + 1;
        float sv[3];
        float pmax = -1e30f;
        #pragma unroll
        for (int r = 0; r < 3; r++){
            int k = lane + r*32;
            float s = -1e30f;
            if (k < nk){
                s = 0.f;
                #pragma unroll
                for (int d = 0; d < 64; d++) s += qs[wid][d]*Ks[k*TW + d];
                s *= 0.125f;
            }
            sv[r] = s;
            pmax = fmaxf(pmax, s);
        }
        for (int o = 16; o; o >>= 1)
            pmax = fmaxf(pmax, __shfl_xor_sync(0xffffffffu, pmax, o));
        float psum = 0.f;
        #pragma unroll
        for (int r = 0; r < 3; r++){
            int k = lane + r*32;
            float e = (k < nk) ? expf(sv[r] - pmax) : 0.f;
            if (k < nk) ps[wid][k] = e;
            psum += e;
        }
        for (int o = 16; o; o >>= 1)
            psum += __shfl_xor_sync(0xffffffffu, psum, o);
        float inv = 1.f/psum;
        __syncwarp();
        float* orow = O + (size_t)(w*TW + j)*DM + h*64;
        for (int d = lane; d < 64; d += 32){
            float a = 0.f;
            for (int k = 0; k < nk; k++) a += ps[wid][k]*Vs[k*TW + d];
            orow[d] = a*inv;
        }
        __syncwarp();
    }
}

// last-query attention (layer 1)
__global__ void attn_last_kernel(const float* __restrict__ Q,
                                 const float* __restrict__ KV,
                                 float* __restrict__ O){
    int w = blockIdx.x, h = blockIdx.y;
    __shared__ float sc[TW];
    __shared__ float qsh[64];
    __shared__ float sinv;
    int tid = threadIdx.x;             // 128
    if (tid < 64) qsh[tid] = Q[(size_t)w*DM + h*64 + tid];
    __syncthreads();
    if (tid < TW){
        const float* kr = KV + (size_t)(w*TW + tid)*1024 + h*64;
        float s = 0.f;
        #pragma unroll
        for (int d = 0; d < 64; d++) s += qsh[d]*kr[d];
        sc[tid] = s*0.125f;
    }
    __syncthreads();
    if (tid == 0){
        float m = -1e30f;
        for (int j = 0; j < TW; j++) m = fmaxf(m, sc[j]);
        float su = 0.f;
        for (int j = 0; j < TW; j++){ float e = expf(sc[j]-m); sc[j] = e; su += e; }
        sinv = 1.f/su;
    }
    __syncthreads();
    if (tid < 64){
        float a = 0.f;
        for (int j = 0; j < TW; j++)
            a += sc[j]*KV[(size_t)(w*TW + j)*1024 + 512 + h*64 + tid];
        O[(size_t)w*DM + h*64 + tid] = a*sinv;
    }
}

// ---------------- host ----------------
extern "C" void kernel_launch(void* const* d_in, const int* in_sizes, int n_in,
                              void* d_out, int out_size){
    const int*   input_ids = (const int*)  d_in[0];
    const float* embedding = (const float*)d_in[1];
    const float* ln1_g = (const float*)d_in[2];
    const float* ln1_b = (const float*)d_in[3];
    const float* wqkv  = (const float*)d_in[4];
    const float* wo    = (const float*)d_in[5];
    const float* ln2_g = (const float*)d_in[6];
    const float* ln2_b = (const float*)d_in[7];
    const float* w1    = (const float*)d_in[8];
    const float* b1    = (const float*)d_in[9];
    const float* w2    = (const float*)d_in[10];
    const float* b2    = (const float*)d_in[11];
    const float* lnf_g = (const float*)d_in[12];
    const float* lnf_b = (const float*)d_in[13];
    const float* pool_q  = (const float*)d_in[14];
    const float* pool_wk = (const float*)d_in[15];
    const float* ssm_win = (const float*)d_in[16];
    const float* ssm_wdt = (const float*)d_in[17];
    const float* ssm_bdt = (const float*)d_in[18];
    const float* ssm_Alog= (const float*)d_in[19];
    const float* ssm_wB  = (const float*)d_in[20];
    const float* ssm_wC  = (const float*)d_in[21];
    const float* ssm_D   = (const float*)d_in[22];
    const float* ssm_wout= (const float*)d_in[23];
    float* out = (float*)d_out;

    float *pX, *pXN, *pW, *pO, *pQl, *pOl, *pXL, *pHL, *pFL;
    cudaGetSymbolAddress((void**)&pX,  g_X);
    cudaGetSymbolAddress((void**)&pXN, g_XN);
    cudaGetSymbolAddress((void**)&pW,  g_wide);
    cudaGetSymbolAddress((void**)&pO,  g_O);
    cudaGetSymbolAddress((void**)&pQl, g_Ql);
    cudaGetSymbolAddress((void**)&pOl, g_Ol);
    cudaGetSymbolAddress((void**)&pXL, g_XL);
    cudaGetSymbolAddress((void**)&pHL, g_HL);
    cudaGetSymbolAddress((void**)&pFL, g_FL);

    init_zero_kernel<<<512, 256>>>();
    build_emb_kernel<<<BSZ*SEQ, 128>>>(input_ids, embedding);
    pwq_kernel<<<1, 512>>>(pool_wk, pool_q);

    // ---- Phase A: 15 sequential SSM writes ----
    for (int k = 1; k <= 15; k++){
        int t = 16*k;
        pool_kernel<<<BSZ, 256>>>(t, k-1);
        for (int l = 0; l < 2; l++){
            ssm_xz_kernel <<<dim3(8, BSZ), 256>>>(ssm_win + (size_t)l*DM*2*DIN);
            ssm_dt_kernel <<<dim3(4, BSZ), 256>>>(ssm_wdt + (size_t)l*DIN*DIN,
                                                  ssm_bdt + (size_t)l*DIN);
            ssm_bc_kernel <<<BSZ, 32>>>(ssm_wB + (size_t)l*DIN*DST,
                                        ssm_wC + (size_t)l*DIN*DST);
            ssm_hy_kernel <<<dim3(4, BSZ), 256>>>(ssm_Alog + (size_t)l*DIN*DST,
                                                  ssm_D + (size_t)l*DIN, l);
            ssm_xup_kernel<<<dim3(2, BSZ), 256>>>(ssm_wout + (size_t)l*DIN*DM);
        }
        copy_ssm_kernel<<<8, 256>>>(k);
    }

    // ---- Phase B: 1024 parallel transformer windows ----
    build_x_kernel<<<NROWS, 128>>>();

    // layer 0 (full)
    ln_kernel<<<NROWS, 256>>>(pX, DM, pXN, DM, ln1_g, ln1_b);
    sgemm_nn<0,false,false><<<dim3(1536/GBN, NROWS/GBM), 256>>>(
        pXN, DM, wqkv, 1536, pW, 1536, nullptr, DM);
    attn_full_kernel<<<dim3(NWIN, NH), 256>>>(pW, pO);
    sgemm_nn<0,true,false><<<dim3(DM/GBN, NROWS/GBM), 256>>>(
        pO, DM, wo, DM, pX, DM, nullptr, DM);
    ln_kernel<<<NROWS, 256>>>(pX, DM, pXN, DM, ln2_g, ln2_b);
    sgemm_nn<1,false,true><<<dim3(DFFN/GBN, NROWS/GBM), 256>>>(
        pXN, DM, w1, DFFN, pW, DFFN, b1, DM);
    sgemm_nn<0,true,true><<<dim3(DM/GBN, NROWS/GBM), 256>>>(
        pW, DFFN, w2, DM, pX, DM, b2, DFFN);

    // layer 1 (K/V at all positions, everything else only last token)
    const float* wqkv1 = wqkv + (size_t)1*DM*1536;
    ln_kernel<<<NROWS, 256>>>(pX, DM, pXN, DM, ln1_g + DM, ln1_b + DM);
    sgemm_nn<0,false,false><<<dim3(1024/GBN, NROWS/GBM), 256>>>(
        pXN, DM, wqkv1 + 512, 1536, pW, 1024, nullptr, DM);               // KV
    sgemm_nn<0,false,false><<<dim3(DM/GBN, NWIN/GBM), 256>>>(
        pXN + (size_t)64*DM, (long long)TW*DM, wqkv1, 1536, pQl, DM, nullptr, DM); // Q last
    attn_last_kernel<<<dim3(NWIN, NH), 128>>>(pQl, pW, pOl);
    sgemm_nn<0,true,false><<<dim3(DM/GBN, NWIN/GBM), 256>>>(
        pOl, DM, wo + (size_t)DM*DM, DM, pX + (size_t)64*DM, (long long)TW*DM,
        nullptr, DM);
    ln_kernel<<<NWIN, 256>>>(pX + (size_t)64*DM, (long long)TW*DM, pXL, DM,
                             ln2_g + DM, ln2_b + DM);
    sgemm_nn<1,false,true><<<dim3(DFFN/GBN, NWIN/GBM), 256>>>(
        pXL, DM, w1 + (size_t)DM*DFFN, DFFN, pHL, DFFN, b1 + DFFN, DM);
    sgemm_nn<0,true,true><<<dim3(DM/GBN, NWIN/GBM), 256>>>(
        pHL, DFFN, w2 + (size_t)DFFN*DM, DM, pX + (size_t)64*DM, (long long)TW*DM,
        b2 + DM, DFFN);

    // final LN (last rows) + tied logits
    ln_kernel<<<NWIN, 256>>>(pX + (size_t)64*DM, (long long)TW*DM, pFL, DM,
                             lnf_g, lnf_b);
    sgemm_nt<<<dim3(VOC/GBN, NWIN/GBM), 256>>>(
        pFL, DM, embedding, DM, out, VOC, DM);
}

// round 3
// speedup vs baseline: 2.8650x; 2.8650x over previous
#include <cuda_runtime.h>
#include <cstddef>

// ---------------- constants ----------------
#define BSZ   4
#define SEQ   256
#define DM    512
#define NH    8
#define TW    65          // window length
#define NWIN  1024        // BSZ*SEQ
#define NROWS 66560       // NWIN*TW
#define VOC   32000
#define DFFN  2048
#define DIN   1024        // ssm d_inner
#define DST   16          // ssm d_state
#define NUNIQ 1085
#define UPAD  1152        // padded unique rows (9*128)

// ---------------- device scratch ----------------
__device__ float g_emb [BSZ*SEQ*DM];
__device__ float g_ssmv[16*BSZ*DM];
__device__ float g_hst [2*BSZ*DIN*DST];
__device__ float g_sx  [BSZ*DM];
__device__ float g_xz  [BSZ*2*DIN];
__device__ float g_dt  [BSZ*DIN];
__device__ float g_Bm  [BSZ*DST];
__device__ float g_Cm  [BSZ*DST];
__device__ float g_y   [BSZ*DIN];
__device__ float g_pwq [DM];

__device__ float g_U   [(size_t)UPAD*DM];
__device__ float g_UN  [(size_t)UPAD*DM];
__device__ float g_QKVU[(size_t)UPAD*1536];

__device__ float g_X   [(size_t)NROWS*DM];    // residual stream
__device__ float g_XN  [(size_t)NROWS*DM];    // LN output
__device__ float g_wide[(size_t)NROWS*DFFN];  // H(2048)/KV(1024) shared
__device__ float g_O   [(size_t)NROWS*DM];    // attn out
__device__ float g_Ql  [(size_t)NWIN*DM];
__device__ float g_Ol  [(size_t)NWIN*DM];
__device__ float g_XL  [(size_t)NWIN*DM];
__device__ float g_HL  [(size_t)NWIN*DFFN];
__device__ float g_FL  [(size_t)NWIN*DM];

// ---------------- device helpers ----------------
__device__ __forceinline__ float softplusf(float x){
    return (x > 20.f) ? x : log1pf(expf(x));
}
__device__ __forceinline__ float geluf(float x){
    float x3 = x*x*x;
    return 0.5f*x*(1.f + tanhf(0.7978845608028654f*(x + 0.044715f*x3)));
}
__device__ __forceinline__ float siluf(float z){
    return z / (1.f + expf(-z));
}
__device__ __forceinline__ unsigned f2tf(float x){
    unsigned r; asm("cvt.rna.tf32.f32 %0, %1;" : "=r"(r) : "f"(x)); return r;
}
__device__ __forceinline__ void mma_tf32(float* c, const unsigned* a, const unsigned* b){
    asm volatile("mma.sync.aligned.m16n8k8.row.col.f32.tf32.tf32.f32 "
        "{%0,%1,%2,%3}, {%4,%5,%6,%7}, {%8,%9}, {%0,%1,%2,%3};"
        : "+f"(c[0]), "+f"(c[1]), "+f"(c[2]), "+f"(c[3])
        : "r"(a[0]), "r"(a[1]), "r"(a[2]), "r"(a[3]), "r"(b[0]), "r"(b[1]));
}

// ---------------- init / embed ----------------
__global__ void init_zero_kernel(){
    int i = blockIdx.x*256 + threadIdx.x;
    if (i < 2*BSZ*DIN*DST) g_hst[i] = 0.f;
    if (i < BSZ*DM)        g_ssmv[i] = 0.f;
}

__global__ void build_emb_kernel(const int* __restrict__ ids,
                                 const float* __restrict__ table){
    int i = blockIdx.x;               // b*SEQ+t
    int id = ids[i];
    const float* src = table + (size_t)id*DM;
    float* dst = g_emb + (size_t)i*DM;
    for (int c = threadIdx.x; c < DM; c += 128) dst[c] = src[c];
}

__global__ void pwq_kernel(const float* __restrict__ wk,
                           const float* __restrict__ q){
    int d = threadIdx.x;              // 512 threads
    float s = 0.f;
    #pragma unroll
    for (int k = 0; k < 64; k++) s += wk[d*64 + k]*q[k];
    g_pwq[d] = s;
}

// ---------------- Phase A: pooling + SSM ----------------
__global__ void pool_kernel(int t, int kprev){
    int b = blockIdx.x;
    __shared__ float sc[80];
    __shared__ float sinv;
    int tid = threadIdx.x;            // 256
    int lane = tid & 31, wid = tid >> 5;
    for (int j = wid; j < TW; j += 8){
        const float* row = nullptr;
        if (j == 0) row = g_ssmv + ((size_t)kprev*BSZ + b)*DM;
        else { int tt = t - 64 + j; if (tt >= 0) row = g_emb + ((size_t)b*SEQ + tt)*DM; }
        float s = 0.f;
        if (row) for (int d = lane; d < DM; d += 32) s += row[d]*g_pwq[d];
        for (int o = 16; o; o >>= 1) s += __shfl_xor_sync(0xffffffffu, s, o);
        if (lane == 0) sc[j] = s*0.125f;
    }
    __syncthreads();
    if (wid == 0){
        float v0 = sc[lane];
        float v1 = sc[lane + 32];
        float v2 = (lane == 0) ? sc[64] : -1e30f;
        float m = fmaxf(v0, fmaxf(v1, v2));
        for (int o = 16; o; o >>= 1) m = fmaxf(m, __shfl_xor_sync(0xffffffffu, m, o));
        float e0 = expf(v0 - m), e1 = expf(v1 - m);
        float e2 = (lane == 0) ? expf(v2 - m) : 0.f;
        float s = e0 + e1 + e2;
        for (int o = 16; o; o >>= 1) s += __shfl_xor_sync(0xffffffffu, s, o);
        sc[lane] = e0; sc[lane + 32] = e1;
        if (lane == 0){ sc[64] = e2; sinv = 1.f/s; }
    }
    __syncthreads();
    for (int d = tid; d < DM; d += 256){
        float acc = sc[0]*g_ssmv[((size_t)kprev*BSZ + b)*DM + d];
        for (int j = 1; j < TW; j++){
            int tt = t - 64 + j;
            if (tt >= 0) acc += sc[j]*g_emb[((size_t)b*SEQ + tt)*DM + d];
        }
        g_sx[b*DM + d] = acc*sinv;
    }
}

__global__ void ssm_xz_kernel(const float* __restrict__ win){
    __shared__ float xs[DM];
    int b = blockIdx.y;
    int c = blockIdx.x*256 + threadIdx.x;       // 0..2047
    xs[threadIdx.x]       = g_sx[b*DM + threadIdx.x];
    xs[threadIdx.x + 256] = g_sx[b*DM + threadIdx.x + 256];
    __syncthreads();
    float s = 0.f;
    #pragma unroll 8
    for (int d = 0; d < DM; d++) s += xs[d]*win[(size_t)d*2048 + c];
    g_xz[b*2048 + c] = s;
}

__global__ void ssm_dt_kernel(const float* __restrict__ wdt,
                              const float* __restrict__ bdt){
    __shared__ float xs[DIN];
    int b = blockIdx.y;
    int c = blockIdx.x*256 + threadIdx.x;       // 0..1023
    for (int i = threadIdx.x; i < DIN; i += 256) xs[i] = g_xz[b*2048 + i];
    __syncthreads();
    float s = bdt[c];
    #pragma unroll 8
    for (int d = 0; d < DIN; d++) s += xs[d]*wdt[(size_t)d*DIN + c];
    g_dt[b*DIN + c] = softplusf(s);
}

__global__ void ssm_bc_kernel(const float* __restrict__ wB,
                              const float* __restrict__ wC){
    int b = blockIdx.x;
    int tid = threadIdx.x;                      // 32
    const float* w = (tid < 16) ? wB : wC;
    int s = tid & 15;
    float acc = 0.f;
    #pragma unroll 4
    for (int d = 0; d < DIN; d++) acc += g_xz[b*2048 + d]*w[d*DST + s];
    if (tid < 16) g_Bm[b*DST + s] = acc; else g_Cm[b*DST + s] = acc;
}

__global__ void ssm_hy_kernel(const float* __restrict__ Alog,
                              const float* __restrict__ Dw, int l){
    int b = blockIdx.y;
    int d = blockIdx.x*256 + threadIdx.x;
    float x1 = g_xz[b*2048 + d];
    float z  = g_xz[b*2048 + DIN + d];
    float dt = g_dt[b*DIN + d];
    float* hp = g_hst + (((size_t)l*BSZ + b)*DIN + d)*DST;
    float y = 0.f;
    #pragma unroll
    for (int s = 0; s < DST; s++){
        float Av = -expf(Alog[d*DST + s]);
        float hv = expf(dt*Av)*hp[s] + dt*g_Bm[b*DST + s]*x1;
        hp[s] = hv;
        y += hv*g_Cm[b*DST + s];
    }
    y += Dw[d]*x1;
    y *= siluf(z);
    g_y[b*DIN + d] = y;
}

__global__ void ssm_xup_kernel(const float* __restrict__ wout, int k, int last){
    __shared__ float ys[DIN];
    int b = blockIdx.y;
    int c = blockIdx.x*256 + threadIdx.x;       // 0..511
    for (int i = threadIdx.x; i < DIN; i += 256) ys[i] = g_y[b*DIN + i];
    __syncthreads();
    float s = 0.f;
    #pragma unroll 8
    for (int d = 0; d < DIN; d++) s += ys[d]*wout[(size_t)d*DM + c];
    float nv = g_sx[b*DM + c] + s;
    g_sx[b*DM + c] = nv;
    if (last) g_ssmv[((size_t)k*BSZ + b)*DM + c] = nv;
}

// ---------------- Phase B: batched transformer ----------------
__global__ void build_uniq_kernel(){
    int u = blockIdx.x;                // 0..1151
    float* dst = g_U + (size_t)u*DM;
    const float* src = nullptr;
    if (u >= 1 && u < 1025) src = g_emb + (size_t)(u-1)*DM;
    else if (u >= 1025 && u < NUNIQ){
        int idx = u - 1025; int k = idx/4 + 1, b = idx & 3;
        src = g_ssmv + ((size_t)k*BSZ + b)*DM;
    }
    for (int c = threadIdx.x; c < DM; c += 128) dst[c] = src ? src[c] : 0.f;
}

__global__ void build_x_kernel(){
    int r = blockIdx.x;                // 0..66559
    int w = r/TW, j = r - w*TW;
    int b = w >> 8, t = w & 255;
    float* dst = g_X + (size_t)r*DM;
    const float* src = nullptr;
    if (j == 0){
        int k = (t >= 17) ? ((t-1) >> 4) : 0;
        if (k) src = g_ssmv + ((size_t)k*BSZ + b)*DM;
    } else {
        int tt = t - 64 + j;
        if (tt >= 0) src = g_emb + ((size_t)b*SEQ + tt)*DM;
    }
    for (int c = threadIdx.x; c < DM; c += 128)
        dst[c] = src ? src[c] : 0.f;
}

__global__ void ln_kernel(const float* __restrict__ in, long long ldi,
                          float* __restrict__ out, long long ldo,
                          const float* __restrict__ gw,
                          const float* __restrict__ bw){
    long long r = blockIdx.x;
    const float* x = in + r*ldi;
    int tid = threadIdx.x;             // 256
    float v0 = x[tid], v1 = x[tid + 256];
    float s = v0 + v1, q = v0*v0 + v1*v1;
    __shared__ float ss[8], sq[8];
    for (int o = 16; o; o >>= 1){
        s += __shfl_xor_sync(0xffffffffu, s, o);
        q += __shfl_xor_sync(0xffffffffu, q, o);
    }
    if ((tid & 31) == 0){ ss[tid >> 5] = s; sq[tid >> 5] = q; }
    __syncthreads();
    if (tid < 8){
        s = ss[tid]; q = sq[tid];
        for (int o = 4; o; o >>= 1){
            s += __shfl_xor_sync(0xffu, s, o);
            q += __shfl_xor_sync(0xffu, q, o);
        }
        if (tid == 0){ ss[0] = s; sq[0] = q; }
    }
    __syncthreads();
    float mu  = ss[0]*(1.f/512.f);
    float var = sq[0]*(1.f/512.f) - mu*mu;
    float inv = rsqrtf(var + 1e-5f);
    float* o = out + r*ldo;
    o[tid]       = (v0 - mu)*inv*gw[tid] + bw[tid];
    o[tid + 256] = (v1 - mu)*inv*gw[tid + 256] + bw[tid + 256];
}

// -------- tf32 tensor-core GEMM --------
// C(MxN) = A(MxK) @ B  (B row-major KxN, or NT: B row-major NxK)
#define TBM 128
#define TBN 128
#define TBK 32
#define TLDA 132
#define TLDB 132

template<int ACT, bool RESID, bool HASBIAS, bool TRANSB, bool SWAPXY>
__global__ __launch_bounds__(256)
void tgemm(const float* __restrict__ A, long long lda,
           const float* __restrict__ B, long long ldb,
           float* __restrict__ C, long long ldc,
           const float* __restrict__ bias, int K){
    __shared__ unsigned As[TBK][TLDA];   // [k][m]
    __shared__ unsigned Bs[TBK][TLDB];   // [k][n]
    int bmt = SWAPXY ? blockIdx.x : blockIdx.y;
    int bnt = SWAPXY ? blockIdx.y : blockIdx.x;
    long long bm = (long long)bmt*TBM, bn = (long long)bnt*TBN;
    int tid = threadIdx.x;
    int lane = tid & 31, wid = tid >> 5;
    int wm = (wid >> 2)*64, wn = (wid & 3)*32;

    float acc[4][4][4];
    #pragma unroll
    for (int i = 0; i < 4; i++)
        #pragma unroll
        for (int j = 0; j < 4; j++)
            #pragma unroll
            for (int r = 0; r < 4; r++) acc[i][j][r] = 0.f;

    for (int k0 = 0; k0 < K; k0 += TBK){
        // load A tile -> As[k][m]
        {
            int m = tid >> 1, kc = (tid & 1)*16;
            const float* ap = A + (bm + m)*lda + k0 + kc;
            #pragma unroll
            for (int j = 0; j < 4; j++){
                float4 v = *(const float4*)(ap + j*4);
                int kq = kc + j*4;
                As[kq+0][m] = f2tf(v.x); As[kq+1][m] = f2tf(v.y);
                As[kq+2][m] = f2tf(v.z); As[kq+3][m] = f2tf(v.w);
            }
        }
        // load B tile -> Bs[k][n]
        if (!TRANSB){
            int kr = tid >> 5, nc = (tid & 31)*4;
            #pragma unroll
            for (int j = 0; j < 4; j++){
                int k = kr + j*8;
                float4 v = *(const float4*)(B + (size_t)(k0+k)*ldb + bn + nc);
                Bs[k][nc+0] = f2tf(v.x); Bs[k][nc+1] = f2tf(v.y);
                Bs[k][nc+2] = f2tf(v.z); Bs[k][nc+3] = f2tf(v.w);
            }
        } else {
            int nr = tid >> 1, kc = (tid & 1)*16;
            const float* bp = B + (bn + nr)*ldb + k0 + kc;
            #pragma unroll
            for (int j = 0; j < 4; j++){
                float4 v = *(const float4*)(bp + j*4);
                int kq = kc + j*4;
                Bs[kq+0][nr] = f2tf(v.x); Bs[kq+1][nr] = f2tf(v.y);
                Bs[kq+2][nr] = f2tf(v.z); Bs[kq+3][nr] = f2tf(v.w);
            }
        }
        __syncthreads();
        #pragma unroll
        for (int kk = 0; kk < 4; kk++){
            int kb = kk*8;
            unsigned af[4][4], bf[4][2];
            #pragma unroll
            for (int mt = 0; mt < 4; mt++){
                int m = wm + mt*16 + (lane >> 2);
                int k = kb + (lane & 3);
                af[mt][0] = As[k][m];
                af[mt][1] = As[k][m+8];
                af[mt][2] = As[k+4][m];
                af[mt][3] = As[k+4][m+8];
            }
            #pragma unroll
            for (int nt = 0; nt < 4; nt++){
                int n = wn + nt*8 + (lane >> 2);
                int k = kb + (lane & 3);
                bf[nt][0] = Bs[k][n];
                bf[nt][1] = Bs[k+4][n];
            }
            #pragma unroll
            for (int mt = 0; mt < 4; mt++)
                #pragma unroll
                for (int nt = 0; nt < 4; nt++)
                    mma_tf32(acc[mt][nt], af[mt], bf[nt]);
        }
        __syncthreads();
    }
    // epilogue
    #pragma unroll
    for (int mt = 0; mt < 4; mt++){
        #pragma unroll
        for (int nt = 0; nt < 4; nt++){
            long long row0 = bm + wm + mt*16 + (lane >> 2);
            long long col  = bn + wn + nt*8 + (lane & 3)*2;
            float b0 = 0.f, b1 = 0.f;
            if (HASBIAS){ b0 = bias[col]; b1 = bias[col+1]; }
            float v00 = acc[mt][nt][0] + b0, v01 = acc[mt][nt][1] + b1;
            float v10 = acc[mt][nt][2] + b0, v11 = acc[mt][nt][3] + b1;
            if (ACT == 1){ v00 = geluf(v00); v01 = geluf(v01);
                           v10 = geluf(v10); v11 = geluf(v11); }
            float* c0 = C + row0*ldc + col;
            float* c1 = C + (row0+8)*ldc + col;
            if (RESID){
                float2 r0 = *(float2*)c0, r1 = *(float2*)c1;
                v00 += r0.x; v01 += r0.y; v10 += r1.x; v11 += r1.y;
            }
            *(float2*)c0 = make_float2(v00, v01);
            *(float2*)c1 = make_float2(v10, v11);
        }
    }
}

// full causal attention (layer 0): per (window, head) block, gathers unique QKV
__global__ __launch_bounds__(256)
void attn_full_kernel(const float* __restrict__ QKVU, float* __restrict__ O){
    int w = blockIdx.x, h = blockIdx.y;
    int b = w >> 8, t = w & 255;
    __shared__ float Ks[TW*TW];
    __shared__ float Vs[TW*TW];
    __shared__ float qs[8][64];
    __shared__ float ps[8][68];
    __shared__ int us[TW];
    int tid = threadIdx.x;
    int lane = tid & 31, wid = tid >> 5;
    if (tid < TW){
        int j = tid, u;
        if (j == 0){
            int k = (t >= 17) ? ((t-1) >> 4) : 0;
            u = k ? (1025 + (k-1)*4 + b) : 0;
        } else {
            int tt = t - 64 + j;
            u = (tt >= 0) ? (1 + b*256 + tt) : 0;
        }
        us[j] = u;
    }
    __syncthreads();
    for (int idx = tid; idx < TW*64; idx += 256){
        int j = idx >> 6, d = idx & 63;
        const float* base = QKVU + (size_t)us[j]*1536 + h*64;
        Ks[j*TW + d] = base[512 + d];
        Vs[j*TW + d] = base[1024 + d];
    }
    __syncthreads();
    for (int j = wid; j < TW; j += 8){
        const float* qb = QKVU + (size_t)us[j]*1536 + h*64;
        qs[wid][lane]      = qb[lane];
        qs[wid][lane + 32] = qb[lane + 32];
        __syncwarp();
        int nk = j + 1;
        float sv[3];
        float pmax = -1e30f;
        #pragma unroll
        for (int r = 0; r < 3; r++){
            int k = lane + r*32;
            float s = -1e30f;
            if (k < nk){
                s = 0.f;
                #pragma unroll
                for (int d = 0; d < 64; d++) s += qs[wid][d]*Ks[k*TW + d];
                s *= 0.125f;
            }
            sv[r] = s;
            pmax = fmaxf(pmax, s);
        }
        for (int o = 16; o; o >>= 1)
            pmax = fmaxf(pmax, __shfl_xor_sync(0xffffffffu, pmax, o));
        float psum = 0.f;
        #pragma unroll
        for (int r = 0; r < 3; r++){
            int k = lane + r*32;
            float e = (k < nk) ? expf(sv[r] - pmax) : 0.f;
            if (k < nk) ps[wid][k] = e;
            psum += e;
        }
        for (int o = 16; o; o >>= 1)
            psum += __shfl_xor_sync(0xffffffffu, psum, o);
        float inv = 1.f/psum;
        __syncwarp();
        float* orow = O + (size_t)(w*TW + j)*DM + h*64;
        for (int d = lane; d < 64; d += 32){
            float a = 0.f;
            for (int k = 0; k < nk; k++) a += ps[wid][k]*Vs[k*TW + d];
            orow[d] = a*inv;
        }
        __syncwarp();
    }
}

// last-query attention (layer 1)
__global__ void attn_last_kernel(const float* __restrict__ Q,
                                 const float* __restrict__ KV,
                                 float* __restrict__ O){
    int w = blockIdx.x, h = blockIdx.y;
    __shared__ float sc[TW];
    __shared__ float qsh[64];
    __shared__ float sinv;
    int tid = threadIdx.x;             // 128
    if (tid < 64) qsh[tid] = Q[(size_t)w*DM + h*64 + tid];
    __syncthreads();
    if (tid < TW){
        const float* kr = KV + (size_t)(w*TW + tid)*1024 + h*64;
        float s = 0.f;
        #pragma unroll
        for (int d = 0; d < 64; d++) s += qsh[d]*kr[d];
        sc[tid] = s*0.125f;
    }
    __syncthreads();
    if (tid == 0){
        float m = -1e30f;
        for (int j = 0; j < TW; j++) m = fmaxf(m, sc[j]);
        float su = 0.f;
        for (int j = 0; j < TW; j++){ float e = expf(sc[j]-m); sc[j] = e; su += e; }
        sinv = 1.f/su;
    }
    __syncthreads();
    if (tid < 64){
        float a = 0.f;
        for (int j = 0; j < TW; j++)
            a += sc[j]*KV[(size_t)(w*TW + j)*1024 + 512 + h*64 + tid];
        O[(size_t)w*DM + h*64 + tid] = a*sinv;
    }
}

// ---------------- host ----------------
extern "C" void kernel_launch(void* const* d_in, const int* in_sizes, int n_in,
                              void* d_out, int out_size){
    const int*   input_ids = (const int*)  d_in[0];
    const float* embedding = (const float*)d_in[1];
    const float* ln1_g = (const float*)d_in[2];
    const float* ln1_b = (const float*)d_in[3];
    const float* wqkv  = (const float*)d_in[4];
    const float* wo    = (const float*)d_in[5];
    const float* ln2_g = (const float*)d_in[6];
    const float* ln2_b = (const float*)d_in[7];
    const float* w1    = (const float*)d_in[8];
    const float* b1    = (const float*)d_in[9];
    const float* w2    = (const float*)d_in[10];
    const float* b2    = (const float*)d_in[11];
    const float* lnf_g = (const float*)d_in[12];
    const float* lnf_b = (const float*)d_in[13];
    const float* pool_q  = (const float*)d_in[14];
    const float* pool_wk = (const float*)d_in[15];
    const float* ssm_win = (const float*)d_in[16];
    const float* ssm_wdt = (const float*)d_in[17];
    const float* ssm_bdt = (const float*)d_in[18];
    const float* ssm_Alog= (const float*)d_in[19];
    const float* ssm_wB  = (const float*)d_in[20];
    const float* ssm_wC  = (const float*)d_in[21];
    const float* ssm_D   = (const float*)d_in[22];
    const float* ssm_wout= (const float*)d_in[23];
    float* out = (float*)d_out;

    float *pX, *pXN, *pW, *pO, *pQl, *pOl, *pXL, *pHL, *pFL, *pU, *pUN, *pQKVU;
    cudaGetSymbolAddress((void**)&pX,  g_X);
    cudaGetSymbolAddress((void**)&pXN, g_XN);
    cudaGetSymbolAddress((void**)&pW,  g_wide);
    cudaGetSymbolAddress((void**)&pO,  g_O);
    cudaGetSymbolAddress((void**)&pQl, g_Ql);
    cudaGetSymbolAddress((void**)&pOl, g_Ol);
    cudaGetSymbolAddress((void**)&pXL, g_XL);
    cudaGetSymbolAddress((void**)&pHL, g_HL);
    cudaGetSymbolAddress((void**)&pFL, g_FL);
    cudaGetSymbolAddress((void**)&pU,  g_U);
    cudaGetSymbolAddress((void**)&pUN, g_UN);
    cudaGetSymbolAddress((void**)&pQKVU, g_QKVU);

    init_zero_kernel<<<512, 256>>>();
    build_emb_kernel<<<BSZ*SEQ, 128>>>(input_ids, embedding);
    pwq_kernel<<<1, 512>>>(pool_wk, pool_q);

    // ---- Phase A: 15 sequential SSM writes ----
    for (int k = 1; k <= 15; k++){
        int t = 16*k;
        pool_kernel<<<BSZ, 256>>>(t, k-1);
        for (int l = 0; l < 2; l++){
            ssm_xz_kernel <<<dim3(8, BSZ), 256>>>(ssm_win + (size_t)l*DM*2*DIN);
            ssm_dt_kernel <<<dim3(4, BSZ), 256>>>(ssm_wdt + (size_t)l*DIN*DIN,
                                                  ssm_bdt + (size_t)l*DIN);
            ssm_bc_kernel <<<BSZ, 32>>>(ssm_wB + (size_t)l*DIN*DST,
                                        ssm_wC + (size_t)l*DIN*DST);
            ssm_hy_kernel <<<dim3(4, BSZ), 256>>>(ssm_Alog + (size_t)l*DIN*DST,
                                                  ssm_D + (size_t)l*DIN, l);
            ssm_xup_kernel<<<dim3(2, BSZ), 256>>>(ssm_wout + (size_t)l*DIN*DM, k, l);
        }
    }

    // ---- Phase B ----
    // unique-row QKV (layer 0)
    build_uniq_kernel<<<UPAD, 128>>>();
    ln_kernel<<<UPAD, 256>>>(pU, DM, pUN, DM, ln1_g, ln1_b);
    tgemm<0,false,false,false,false><<<dim3(1536/TBN, UPAD/TBM), 256>>>(
        pUN, DM, wqkv, 1536, pQKVU, 1536, nullptr, DM);

    build_x_kernel<<<NROWS, 128>>>();
    attn_full_kernel<<<dim3(NWIN, NH), 256>>>(pQKVU, pO);
    tgemm<0,true,false,false,false><<<dim3(DM/TBN, NROWS/TBM), 256>>>(
        pO, DM, wo, DM, pX, DM, nullptr, DM);
    ln_kernel<<<NROWS, 256>>>(pX, DM, pXN, DM, ln2_g, ln2_b);
    tgemm<1,false,true,false,false><<<dim3(DFFN/TBN, NROWS/TBM), 256>>>(
        pXN, DM, w1, DFFN, pW, DFFN, b1, DM);
    tgemm<0,true,true,false,false><<<dim3(DM/TBN, NROWS/TBM), 256>>>(
        pW, DFFN, w2, DM, pX, DM, b2, DFFN);

    // layer 1 (K/V at all positions, everything else only last token)
    const float* wqkv1 = wqkv + (size_t)1*DM*1536;
    ln_kernel<<<NROWS, 256>>>(pX, DM, pXN, DM, ln1_g + DM, ln1_b + DM);
    tgemm<0,false,false,false,false><<<dim3(1024/TBN, NROWS/TBM), 256>>>(
        pXN, DM, wqkv1 + 512, 1536, pW, 1024, nullptr, DM);               // KV
    tgemm<0,false,false,false,false><<<dim3(DM/TBN, NWIN/TBM), 256>>>(
        pXN + (size_t)64*DM, (long long)TW*DM, wqkv1, 1536, pQl, DM, nullptr, DM); // Q last
    attn_last_kernel<<<dim3(NWIN, NH), 128>>>(pQl, pW, pOl);
    tgemm<0,true,false,false,false><<<dim3(DM/TBN, NWIN/TBM), 256>>>(
        pOl, DM, wo + (size_t)DM*DM, DM, pX + (size_t)64*DM, (long long)TW*DM,
        nullptr, DM);
    ln_kernel<<<NWIN, 256>>>(pX + (size_t)64*DM, (long long)TW*DM, pXL, DM,
                             ln2_g + DM, ln2_b + DM);
    tgemm<1,false,true,false,false><<<dim3(DFFN/TBN, NWIN/TBM), 256>>>(
        pXL, DM, w1 + (size_t)DM*DFFN, DFFN, pHL, DFFN, b1 + DFFN, DM);
    tgemm<0,true,true,false,false><<<dim3(DM/TBN, NWIN/TBM), 256>>>(
        pHL, DFFN, w2 + (size_t)DFFN*DM, DM, pX + (size_t)64*DM, (long long)TW*DM,
        b2 + DM, DFFN);

    // final LN (last rows) + tied logits (NT, swapped grid for B reuse)
    ln_kernel<<<NWIN, 256>>>(pX + (size_t)64*DM, (long long)TW*DM, pFL, DM,
                             lnf_g, lnf_b);
    tgemm<0,false,false,true,true><<<dim3(NWIN/TBM, VOC/TBN), 256>>>(
        pFL, DM, embedding, DM, out, VOC, nullptr, DM);
}

// round 4
// speedup vs baseline: 3.4929x; 1.2191x over previous
#include <cuda_runtime.h>
#include <cstddef>

// ---------------- constants ----------------
#define BSZ   4
#define SEQ   256
#define DM    512
#define NH    8
#define TW    65          // window length
#define NWIN  1024        // BSZ*SEQ
#define NROWS 66560       // NWIN*TW
#define VOC   32000
#define DFFN  2048
#define DIN   1024        // ssm d_inner
#define DST   16          // ssm d_state
#define NUNIQ 1085
#define UPAD  1152        // padded unique rows (9*128)

// ---------------- device scratch ----------------
__device__ float g_emb [BSZ*SEQ*DM];
__device__ float g_ssmv[16*BSZ*DM];
__device__ float g_hst [2*BSZ*DIN*DST];
__device__ float g_sx  [BSZ*DM];
__device__ float g_xz  [BSZ*2*DIN];
__device__ float g_dt  [BSZ*DIN];
__device__ float g_Bm  [BSZ*DST];
__device__ float g_Cm  [BSZ*DST];
__device__ float g_y   [BSZ*DIN];
__device__ float g_pwq [DM];

__device__ float g_U   [(size_t)UPAD*DM];
__device__ float g_UN  [(size_t)UPAD*DM];
__device__ float g_QKVU[(size_t)UPAD*1536];

__device__ float g_X   [(size_t)NROWS*DM];    // residual stream
__device__ float g_XN  [(size_t)NROWS*DM];    // LN output (tf32-rounded)
__device__ float g_wide[(size_t)NROWS*DFFN];  // H(2048)/KV(1024) shared
__device__ float g_O   [(size_t)NROWS*DM];    // attn out (tf32-rounded)
__device__ float g_Ql  [(size_t)NWIN*DM];
__device__ float g_Ol  [(size_t)NWIN*DM];
__device__ float g_XL  [(size_t)NWIN*DM];
__device__ float g_HL  [(size_t)NWIN*DFFN];
__device__ float g_FL  [(size_t)NWIN*DM];

// tf32-rounded weight copies
__device__ float g_wqkv_r[2*DM*1536];
__device__ float g_wo_r  [2*DM*DM];
__device__ float g_w1_r  [2*DM*DFFN];
__device__ float g_w2_r  [2*DFFN*DM];
__device__ float g_embr  [(size_t)VOC*DM];

// ---------------- device helpers ----------------
__device__ __forceinline__ float softplusf(float x){
    return (x > 20.f) ? x : log1pf(expf(x));
}
__device__ __forceinline__ float geluf(float x){
    float x3 = x*x*x;
    return 0.5f*x*(1.f + tanhf(0.7978845608028654f*(x + 0.044715f*x3)));
}
__device__ __forceinline__ float siluf(float z){
    return z / (1.f + expf(-z));
}
__device__ __forceinline__ unsigned f2tf(float x){
    unsigned r; asm("cvt.rna.tf32.f32 %0, %1;" : "=r"(r) : "f"(x)); return r;
}
__device__ __forceinline__ float f2tff(float x){
    return __uint_as_float(f2tf(x));
}
__device__ __forceinline__ void mma_tf32(float* c, const unsigned* a, const unsigned* b){
    asm volatile("mma.sync.aligned.m16n8k8.row.col.f32.tf32.tf32.f32 "
        "{%0,%1,%2,%3}, {%4,%5,%6,%7}, {%8,%9}, {%0,%1,%2,%3};"
        : "+f"(c[0]), "+f"(c[1]), "+f"(c[2]), "+f"(c[3])
        : "r"(a[0]), "r"(a[1]), "r"(a[2]), "r"(a[3]), "r"(b[0]), "r"(b[1]));
}
__device__ __forceinline__ void cpa16(unsigned dst, const void* src){
    asm volatile("cp.async.cg.shared.global [%0], [%1], 16;" :: "r"(dst), "l"(src));
}
#define CP_COMMIT() asm volatile("cp.async.commit_group;")
#define CP_WAIT1()  asm volatile("cp.async.wait_group 1;")
#define CP_WAIT0()  asm volatile("cp.async.wait_group 0;")

// ---------------- init / embed / round ----------------
__global__ void init_zero_kernel(){
    int i = blockIdx.x*256 + threadIdx.x;
    if (i < 2*BSZ*DIN*DST) g_hst[i] = 0.f;
    if (i < BSZ*DM)        g_ssmv[i] = 0.f;
}

__global__ void round_kernel(const float* __restrict__ src,
                             float* __restrict__ dst, int n){
    int i = blockIdx.x*256 + threadIdx.x;
    int stride = gridDim.x*256;
    for (; i < n; i += stride) dst[i] = f2tff(src[i]);
}

__global__ void build_emb_kernel(const int* __restrict__ ids,
                                 const float* __restrict__ table){
    int i = blockIdx.x;               // b*SEQ+t
    int id = ids[i];
    const float* src = table + (size_t)id*DM;
    float* dst = g_emb + (size_t)i*DM;
    for (int c = threadIdx.x; c < DM; c += 128) dst[c] = src[c];
}

__global__ void pwq_kernel(const float* __restrict__ wk,
                           const float* __restrict__ q){
    int d = threadIdx.x;              // 512 threads
    float s = 0.f;
    #pragma unroll
    for (int k = 0; k < 64; k++) s += wk[d*64 + k]*q[k];
    g_pwq[d] = s;
}

// ---------------- Phase A: pooling + SSM ----------------
__global__ void pool_kernel(int t, int kprev){
    int b = blockIdx.x;
    __shared__ float sc[80];
    __shared__ float sinv;
    int tid = threadIdx.x;            // 512
    int lane = tid & 31, wid = tid >> 5;   // 16 warps
    for (int j = wid; j < TW; j += 16){
        const float* row = nullptr;
        if (j == 0) row = g_ssmv + ((size_t)kprev*BSZ + b)*DM;
        else { int tt = t - 64 + j; if (tt >= 0) row = g_emb + ((size_t)b*SEQ + tt)*DM; }
        float s = 0.f;
        if (row) for (int d = lane; d < DM; d += 32) s += row[d]*g_pwq[d];
        for (int o = 16; o; o >>= 1) s += __shfl_xor_sync(0xffffffffu, s, o);
        if (lane == 0) sc[j] = s*0.125f;
    }
    __syncthreads();
    if (wid == 0){
        float v0 = sc[lane];
        float v1 = sc[lane + 32];
        float v2 = (lane == 0) ? sc[64] : -1e30f;
        float m = fmaxf(v0, fmaxf(v1, v2));
        for (int o = 16; o; o >>= 1) m = fmaxf(m, __shfl_xor_sync(0xffffffffu, m, o));
        float e0 = expf(v0 - m), e1 = expf(v1 - m);
        float e2 = (lane == 0) ? expf(v2 - m) : 0.f;
        float s = e0 + e1 + e2;
        for (int o = 16; o; o >>= 1) s += __shfl_xor_sync(0xffffffffu, s, o);
        sc[lane] = e0; sc[lane + 32] = e1;
        if (lane == 0){ sc[64] = e2; sinv = 1.f/s; }
    }
    __syncthreads();
    {
        int d = tid;                  // one column per thread, coalesced j-loop
        float acc = sc[0]*g_ssmv[((size_t)kprev*BSZ + b)*DM + d];
        int j0 = (t >= 63) ? 1 : (64 - t);
        const float* ebase = g_emb + ((size_t)b*SEQ + (t - 64))*DM + d;
        #pragma unroll 4
        for (int j = j0; j < TW; j++)
            acc += sc[j]*ebase[(size_t)j*DM];
        g_sx[b*DM + d] = acc*sinv;
    }
}

__global__ void ssm_xz_kernel(const float* __restrict__ win){
    __shared__ float xs[DM];
    int b = blockIdx.y;
    int c = blockIdx.x*256 + threadIdx.x;       // 0..2047
    xs[threadIdx.x]       = g_sx[b*DM + threadIdx.x];
    xs[threadIdx.x + 256] = g_sx[b*DM + threadIdx.x + 256];
    __syncthreads();
    float s = 0.f;
    #pragma unroll 8
    for (int d = 0; d < DM; d++) s += xs[d]*win[(size_t)d*2048 + c];
    g_xz[b*2048 + c] = s;
}

__global__ void ssm_dt_kernel(const float* __restrict__ wdt,
                              const float* __restrict__ bdt){
    __shared__ float xs[DIN];
    int b = blockIdx.y;
    int c = blockIdx.x*256 + threadIdx.x;       // 0..1023
    for (int i = threadIdx.x; i < DIN; i += 256) xs[i] = g_xz[b*2048 + i];
    __syncthreads();
    float s = bdt[c];
    #pragma unroll 8
    for (int d = 0; d < DIN; d++) s += xs[d]*wdt[(size_t)d*DIN + c];
    g_dt[b*DIN + c] = softplusf(s);
}

__global__ void ssm_bc_kernel(const float* __restrict__ wB,
                              const float* __restrict__ wC){
    int b = blockIdx.x;
    int tid = threadIdx.x;                      // 32
    const float* w = (tid < 16) ? wB : wC;
    int s = tid & 15;
    float acc = 0.f;
    #pragma unroll 4
    for (int d = 0; d < DIN; d++) acc += g_xz[b*2048 + d]*w[d*DST + s];
    if (tid < 16) g_Bm[b*DST + s] = acc; else g_Cm[b*DST + s] = acc;
}

__global__ void ssm_hy_kernel(const float* __restrict__ Alog,
                              const float* __restrict__ Dw, int l){
    int b = blockIdx.y;
    int d = blockIdx.x*256 + threadIdx.x;
    float x1 = g_xz[b*2048 + d];
    float z  = g_xz[b*2048 + DIN + d];
    float dt = g_dt[b*DIN + d];
    float* hp = g_hst + (((size_t)l*BSZ + b)*DIN + d)*DST;
    float y = 0.f;
    #pragma unroll
    for (int s = 0; s < DST; s++){
        float Av = -expf(Alog[d*DST + s]);
        float hv = expf(dt*Av)*hp[s] + dt*g_Bm[b*DST + s]*x1;
        hp[s] = hv;
        y += hv*g_Cm[b*DST + s];
    }
    y += Dw[d]*x1;
    y *= siluf(z);
    g_y[b*DIN + d] = y;
}

__global__ void ssm_xup_kernel(const float* __restrict__ wout, int k, int last){
    __shared__ float ys[DIN];
    int b = blockIdx.y;
    int c = blockIdx.x*256 + threadIdx.x;       // 0..511
    for (int i = threadIdx.x; i < DIN; i += 256) ys[i] = g_y[b*DIN + i];
    __syncthreads();
    float s = 0.f;
    #pragma unroll 8
    for (int d = 0; d < DIN; d++) s += ys[d]*wout[(size_t)d*DM + c];
    float nv = g_sx[b*DM + c] + s;
    g_sx[b*DM + c] = nv;
    if (last) g_ssmv[((size_t)k*BSZ + b)*DM + c] = nv;
}

// ---------------- Phase B: batched transformer ----------------
__global__ void build_uniq_kernel(){
    int u = blockIdx.x;                // 0..1151
    float* dst = g_U + (size_t)u*DM;
    const float* src = nullptr;
    if (u >= 1 && u < 1025) src = g_emb + (size_t)(u-1)*DM;
    else if (u >= 1025 && u < NUNIQ){
        int idx = u - 1025; int k = idx/4 + 1, b = idx & 3;
        src = g_ssmv + ((size_t)k*BSZ + b)*DM;
    }
    for (int c = threadIdx.x; c < DM; c += 128) dst[c] = src ? src[c] : 0.f;
}

__global__ void build_x_kernel(){
    int r = blockIdx.x;                // 0..66559
    int w = r/TW, j = r - w*TW;
    int b = w >> 8, t = w & 255;
    float* dst = g_X + (size_t)r*DM;
    const float* src = nullptr;
    if (j == 0){
        int k = (t >= 17) ? ((t-1) >> 4) : 0;
        if (k) src = g_ssmv + ((size_t)k*BSZ + b)*DM;
    } else {
        int tt = t - 64 + j;
        if (tt >= 0) src = g_emb + ((size_t)b*SEQ + tt)*DM;
    }
    for (int c = threadIdx.x; c < DM; c += 128)
        dst[c] = src ? src[c] : 0.f;
}

// LayerNorm; output rounded to tf32 bit pattern (all LN outputs feed GEMMs)
__global__ void ln_kernel(const float* __restrict__ in, long long ldi,
                          float* __restrict__ out, long long ldo,
                          const float* __restrict__ gw,
                          const float* __restrict__ bw){
    long long r = blockIdx.x;
    const float* x = in + r*ldi;
    int tid = threadIdx.x;             // 256
    float v0 = x[tid], v1 = x[tid + 256];
    float s = v0 + v1, q = v0*v0 + v1*v1;
    __shared__ float ss[8], sq[8];
    for (int o = 16; o; o >>= 1){
        s += __shfl_xor_sync(0xffffffffu, s, o);
        q += __shfl_xor_sync(0xffffffffu, q, o);
    }
    if ((tid & 31) == 0){ ss[tid >> 5] = s; sq[tid >> 5] = q; }
    __syncthreads();
    if (tid < 8){
        s = ss[tid]; q = sq[tid];
        for (int o = 4; o; o >>= 1){
            s += __shfl_xor_sync(0xffu, s, o);
            q += __shfl_xor_sync(0xffu, q, o);
        }
        if (tid == 0){ ss[0] = s; sq[0] = q; }
    }
    __syncthreads();
    float mu  = ss[0]*(1.f/512.f);
    float var = sq[0]*(1.f/512.f) - mu*mu;
    float inv = rsqrtf(var + 1e-5f);
    float* o = out + r*ldo;
    o[tid]       = f2tff((v0 - mu)*inv*gw[tid] + bw[tid]);
    o[tid + 256] = f2tff((v1 - mu)*inv*gw[tid + 256] + bw[tid + 256]);
}

// -------- pipelined tf32 tensor-core GEMM --------
// C(MxN) = A(MxK) @ B (row-major KxN; TRANSB: B row-major NxK)
// Operands must already be tf32-rounded fp32. BM=BN=128, BK=32.
#define ALD 36          // As row stride (u32): [m][k], pad 4
#define BLD 132         // Bs row stride notrans: [k][n], pad 4
#define ASZ (128*ALD)   // 4608
#define BSZN (32*BLD)   // 4224
#define BSZT (128*ALD)  // 4608

template<int ACT, bool RESID, bool HASBIAS, bool TRANSB, bool SWAPXY, bool OUTTF>
__global__ __launch_bounds__(256)
void tgemm(const float* __restrict__ A, long long lda,
           const float* __restrict__ B, long long ldb,
           float* __restrict__ C, long long ldc,
           const float* __restrict__ bias, int K){
    extern __shared__ unsigned sh[];
    unsigned* As = sh;                       // [2][ASZ]
    unsigned* Bs = sh + 2*ASZ;               // [2][BSZN or BSZT]
    constexpr int BSZE = TRANSB ? BSZT : BSZN;

    int bmt = SWAPXY ? blockIdx.x : blockIdx.y;
    int bnt = SWAPXY ? blockIdx.y : blockIdx.x;
    long long bm = (long long)bmt*128, bn = (long long)bnt*128;
    int tid = threadIdx.x;
    int lane = tid & 31, wid = tid >> 5;
    int g = lane >> 2, r = lane & 3;
    int wm = (wid >> 2)*64, wn = (wid & 3)*32;

    // load-thread mappings
    int a_m = tid >> 3, a_s4 = (tid & 7)*4;          // + 32*i rows
    const float* Abase = A + (bm + a_m)*lda + a_s4;
    unsigned a_dst = (unsigned)__cvta_generic_to_shared(As) + (a_m*ALD + a_s4)*4u;

    const float* Bbase;
    unsigned b_dst;
    if (TRANSB){
        int b_n = tid >> 3, b_s4 = (tid & 7)*4;
        Bbase = B + (bn + b_n)*ldb + b_s4;
        b_dst = (unsigned)__cvta_generic_to_shared(Bs) + (b_n*ALD + b_s4)*4u;
    } else {
        int b_k = tid >> 5, b_s4 = (tid & 31)*4;
        Bbase = B + (size_t)b_k*ldb + bn + b_s4;
        b_dst = (unsigned)__cvta_generic_to_shared(Bs) + (b_k*BLD + b_s4)*4u;
    }

    float acc[4][4][4];
    #pragma unroll
    for (int i = 0; i < 4; i++)
        #pragma unroll
        for (int j = 0; j < 4; j++)
            #pragma unroll
            for (int q = 0; q < 4; q++) acc[i][j][q] = 0.f;

    int nkt = K >> 5;

    // prologue: stage 0
    {
        #pragma unroll
        for (int i = 0; i < 4; i++)
            cpa16(a_dst + i*32u*ALD*4u, Abase + (size_t)32*i*lda);
        if (TRANSB){
            #pragma unroll
            for (int i = 0; i < 4; i++)
                cpa16(b_dst + i*32u*ALD*4u, Bbase + (size_t)32*i*ldb);
        } else {
            #pragma unroll
            for (int i = 0; i < 4; i++)
                cpa16(b_dst + i*8u*BLD*4u, Bbase + (size_t)8*i*ldb);
        }
        CP_COMMIT();
    }

    for (int kt = 0; kt < nkt; kt++){
        int cur = kt & 1;
        if (kt + 1 < nkt){
            int nxt = cur ^ 1;
            long long ko = (long long)(kt + 1)*32;
            unsigned ad = a_dst + (unsigned)nxt*ASZ*4u;
            #pragma unroll
            for (int i = 0; i < 4; i++)
                cpa16(ad + i*32u*ALD*4u, Abase + (size_t)32*i*lda + ko);
            unsigned bd = b_dst + (unsigned)nxt*BSZE*4u;
            if (TRANSB){
                #pragma unroll
                for (int i = 0; i < 4; i++)
                    cpa16(bd + i*32u*ALD*4u, Bbase + (size_t)32*i*ldb + ko);
            } else {
                #pragma unroll
                for (int i = 0; i < 4; i++)
                    cpa16(bd + i*8u*BLD*4u, Bbase + (size_t)(8*i + kt*32 + 32)*ldb - (size_t)kt*32*ldb + (size_t)kt*32*ldb);
            }
            CP_COMMIT();
            CP_WAIT1();
        } else {
            CP_WAIT0();
        }
        __syncthreads();

        const unsigned* Ab = As + cur*ASZ;
        const unsigned* Bb = Bs + cur*BSZE;
        #pragma unroll
        for (int kk = 0; kk < 4; kk++){
            int kb = kk*8;
            unsigned af[4][4], bf[4][2];
            #pragma unroll
            for (int mt = 0; mt < 4; mt++){
                int m0 = wm + mt*16 + g;
                af[mt][0] = Ab[m0*ALD + kb + r];
                af[mt][1] = Ab[(m0+8)*ALD + kb + r];
                af[mt][2] = Ab[m0*ALD + kb + r + 4];
                af[mt][3] = Ab[(m0+8)*ALD + kb + r + 4];
            }
            #pragma unroll
            for (int nt = 0; nt < 4; nt++){
                int n0 = wn + nt*8 + g;
                if (TRANSB){
                    bf[nt][0] = Bb[n0*ALD + kb + r];
                    bf[nt][1] = Bb[n0*ALD + kb + r + 4];
                } else {
                    bf[nt][0] = Bb[(kb+r)*BLD + n0];
                    bf[nt][1] = Bb[(kb+r+4)*BLD + n0];
                }
            }
            #pragma unroll
            for (int mt = 0; mt < 4; mt++)
                #pragma unroll
                for (int nt = 0; nt < 4; nt++)
                    mma_tf32(acc[mt][nt], af[mt], bf[nt]);
        }
        __syncthreads();
    }

    // epilogue
    #pragma unroll
    for (int mt = 0; mt < 4; mt++){
        #pragma unroll
        for (int nt = 0; nt < 4; nt++){
            long long row0 = bm + wm + mt*16 + g;
            long long col  = bn + wn + nt*8 + r*2;
            float b0 = 0.f, b1 = 0.f;
            if (HASBIAS){ b0 = bias[col]; b1 = bias[col+1]; }
            float v00 = acc[mt][nt][0] + b0, v01 = acc[mt][nt][1] + b1;
            float v10 = acc[mt][nt][2] + b0, v11 = acc[mt][nt][3] + b1;
            if (ACT == 1){ v00 = geluf(v00); v01 = geluf(v01);
                           v10 = geluf(v10); v11 = geluf(v11); }
            float* c0 = C + row0*ldc + col;
            float* c1 = C + (row0+8)*ldc + col;
            if (RESID){
                float2 r0 = *(float2*)c0, r1 = *(float2*)c1;
                v00 += r0.x; v01 += r0.y; v10 += r1.x; v11 += r1.y;
            }
            if (OUTTF){ v00 = f2tff(v00); v01 = f2tff(v01);
                        v10 = f2tff(v10); v11 = f2tff(v11); }
            *(float2*)c0 = make_float2(v00, v01);
            *(float2*)c1 = make_float2(v10, v11);
        }
    }
}

// full causal attention (layer 0): per (window, head) block, gathers unique QKV
__global__ __launch_bounds__(256)
void attn_full_kernel(const float* __restrict__ QKVU, float* __restrict__ O){
    int w = blockIdx.x, h = blockIdx.y;
    int b = w >> 8, t = w & 255;
    __shared__ float Ks[TW*TW];
    __shared__ float Vs[TW*TW];
    __shared__ float qs[8][64];
    __shared__ float ps[8][68];
    __shared__ int us[TW];
    int tid = threadIdx.x;
    int lane = tid & 31, wid = tid >> 5;
    if (tid < TW){
        int j = tid, u;
        if (j == 0){
            int k = (t >= 17) ? ((t-1) >> 4) : 0;
            u = k ? (1025 + (k-1)*4 + b) : 0;
        } else {
            int tt = t - 64 + j;
            u = (tt >= 0) ? (1 + b*256 + tt) : 0;
        }
        us[j] = u;
    }
    __syncthreads();
    for (int idx = tid; idx < TW*64; idx += 256){
        int j = idx >> 6, d = idx & 63;
        const float* base = QKVU + (size_t)us[j]*1536 + h*64;
        Ks[j*TW + d] = base[512 + d];
        Vs[j*TW + d] = base[1024 + d];
    }
    __syncthreads();
    for (int j = wid; j < TW; j += 8){
        const float* qb = QKVU + (size_t)us[j]*1536 + h*64;
        qs[wid][lane]      = qb[lane];
        qs[wid][lane + 32] = qb[lane + 32];
        __syncwarp();
        int nk = j + 1;
        float sv[3];
        float pmax = -1e30f;
        #pragma unroll
        for (int r = 0; r < 3; r++){
            int k = lane + r*32;
            float s = -1e30f;
            if (k < nk){
                s = 0.f;
                #pragma unroll
                for (int d = 0; d < 64; d++) s += qs[wid][d]*Ks[k*TW + d];
                s *= 0.125f;
            }
            sv[r] = s;
            pmax = fmaxf(pmax, s);
        }
        for (int o = 16; o; o >>= 1)
            pmax = fmaxf(pmax, __shfl_xor_sync(0xffffffffu, pmax, o));
        float psum = 0.f;
        #pragma unroll
        for (int r = 0; r < 3; r++){
            int k = lane + r*32;
            float e = (k < nk) ? expf(sv[r] - pmax) : 0.f;
            if (k < nk) ps[wid][k] = e;
            psum += e;
        }
        for (int o = 16; o; o >>= 1)
            psum += __shfl_xor_sync(0xffffffffu, psum, o);
        float inv = 1.f/psum;
        __syncwarp();
        float* orow = O + (size_t)(w*TW + j)*DM + h*64;
        for (int d = lane; d < 64; d += 32){
            float a = 0.f;
            for (int k = 0; k < nk; k++) a += ps[wid][k]*Vs[k*TW + d];
            orow[d] = f2tff(a*inv);
        }
        __syncwarp();
    }
}

// last-query attention (layer 1)
__global__ void attn_last_kernel(const float* __restrict__ Q,
                                 const float* __restrict__ KV,
                                 float* __restrict__ O){
    int w = blockIdx.x, h = blockIdx.y;
    __shared__ float sc[TW];
    __shared__ float qsh[64];
    __shared__ float sinv;
    int tid = threadIdx.x;             // 128
    if (tid < 64) qsh[tid] = Q[(size_t)w*DM + h*64 + tid];
    __syncthreads();
    if (tid < TW){
        const float* kr = KV + (size_t)(w*TW + tid)*1024 + h*64;
        float s = 0.f;
        #pragma unroll
        for (int d = 0; d < 64; d++) s += qsh[d]*kr[d];
        sc[tid] = s*0.125f;
    }
    __syncthreads();
    if (tid == 0){
        float m = -1e30f;
        for (int j = 0; j < TW; j++) m = fmaxf(m, sc[j]);
        float su = 0.f;
        for (int j = 0; j < TW; j++){ float e = expf(sc[j]-m); sc[j] = e; su += e; }
        sinv = 1.f/su;
    }
    __syncthreads();
    if (tid < 64){
        float a = 0.f;
        for (int j = 0; j < TW; j++)
            a += sc[j]*KV[(size_t)(w*TW + j)*1024 + 512 + h*64 + tid];
        O[(size_t)w*DM + h*64 + tid] = f2tff(a*sinv);
    }
}

// ---------------- host ----------------
template<int ACT, bool RESID, bool HASBIAS, bool TRANSB, bool SWAPXY, bool OUTTF>
static void launch_tgemm(dim3 grid, const float* A, long long lda,
                         const float* B, long long ldb,
                         float* C, long long ldc,
                         const float* bias, int K){
    constexpr int BSZE = TRANSB ? BSZT : BSZN;
    int smem = (2*ASZ + 2*BSZE)*4;
    static bool configured = false;
    cudaFuncSetAttribute(tgemm<ACT,RESID,HASBIAS,TRANSB,SWAPXY,OUTTF>,
                         cudaFuncAttributeMaxDynamicSharedMemorySize, smem);
    (void)configured;
    tgemm<ACT,RESID,HASBIAS,TRANSB,SWAPXY,OUTTF><<<grid, 256, smem>>>(
        A, lda, B, ldb, C, ldc, bias, K);
}

extern "C" void kernel_launch(void* const* d_in, const int* in_sizes, int n_in,
                              void* d_out, int out_size){
    const int*   input_ids = (const int*)  d_in[0];
    const float* embedding = (const float*)d_in[1];
    const float* ln1_g = (const float*)d_in[2];
    const float* ln1_b = (const float*)d_in[3];
    const float* wqkv  = (const float*)d_in[4];
    const float* wo    = (const float*)d_in[5];
    const float* ln2_g = (const float*)d_in[6];
    const float* ln2_b = (const float*)d_in[7];
    const float* w1    = (const float*)d_in[8];
    const float* b1    = (const float*)d_in[9];
    const float* w2    = (const float*)d_in[10];
    const float* b2    = (const float*)d_in[11];
    const float* lnf_g = (const float*)d_in[12];
    const float* lnf_b = (const float*)d_in[13];
    const float* pool_q  = (const float*)d_in[14];
    const float* pool_wk = (const float*)d_in[15];
    const float* ssm_win = (const float*)d_in[16];
    const float* ssm_wdt = (const float*)d_in[17];
    const float* ssm_bdt = (const float*)d_in[18];
    const float* ssm_Alog= (const float*)d_in[19];
    const float* ssm_wB  = (const float*)d_in[20];
    const float* ssm_wC  = (const float*)d_in[21];
    const float* ssm_D   = (const float*)d_in[22];
    const float* ssm_wout= (const float*)d_in[23];
    float* out = (float*)d_out;

    float *pX, *pXN, *pW, *pO, *pQl, *pOl, *pXL, *pHL, *pFL, *pU, *pUN, *pQKVU;
    float *pWqkvR, *pWoR, *pW1R, *pW2R, *pEmbR;
    cudaGetSymbolAddress((void**)&pX,  g_X);
    cudaGetSymbolAddress((void**)&pXN, g_XN);
    cudaGetSymbolAddress((void**)&pW,  g_wide);
    cudaGetSymbolAddress((void**)&pO,  g_O);
    cudaGetSymbolAddress((void**)&pQl, g_Ql);
    cudaGetSymbolAddress((void**)&pOl, g_Ol);
    cudaGetSymbolAddress((void**)&pXL, g_XL);
    cudaGetSymbolAddress((void**)&pHL, g_HL);
    cudaGetSymbolAddress((void**)&pFL, g_FL);
    cudaGetSymbolAddress((void**)&pU,  g_U);
    cudaGetSymbolAddress((void**)&pUN, g_UN);
    cudaGetSymbolAddress((void**)&pQKVU, g_QKVU);
    cudaGetSymbolAddress((void**)&pWqkvR, g_wqkv_r);
    cudaGetSymbolAddress((void**)&pWoR, g_wo_r);
    cudaGetSymbolAddress((void**)&pW1R, g_w1_r);
    cudaGetSymbolAddress((void**)&pW2R, g_w2_r);
    cudaGetSymbolAddress((void**)&pEmbR, g_embr);

    init_zero_kernel<<<512, 256>>>();
    build_emb_kernel<<<BSZ*SEQ, 128>>>(input_ids, embedding);
    pwq_kernel<<<1, 512>>>(pool_wk, pool_q);

    // round weights to tf32 once
    round_kernel<<<1024, 256>>>(wqkv, pWqkvR, 2*DM*1536);
    round_kernel<<<512, 256>>>(wo, pWoR, 2*DM*DM);
    round_kernel<<<1024, 256>>>(w1, pW1R, 2*DM*DFFN);
    round_kernel<<<1024, 256>>>(w2, pW2R, 2*DFFN*DM);
    round_kernel<<<4096, 256>>>(embedding, pEmbR, VOC*DM);

    // ---- Phase A: 15 sequential SSM writes ----
    for (int k = 1; k <= 15; k++){
        int t = 16*k;
        pool_kernel<<<BSZ, 512>>>(t, k-1);
        for (int l = 0; l < 2; l++){
            ssm_xz_kernel <<<dim3(8, BSZ), 256>>>(ssm_win + (size_t)l*DM*2*DIN);
            ssm_dt_kernel <<<dim3(4, BSZ), 256>>>(ssm_wdt + (size_t)l*DIN*DIN,
                                                  ssm_bdt + (size_t)l*DIN);
            ssm_bc_kernel <<<BSZ, 32>>>(ssm_wB + (size_t)l*DIN*DST,
                                        ssm_wC + (size_t)l*DIN*DST);
            ssm_hy_kernel <<<dim3(4, BSZ), 256>>>(ssm_Alog + (size_t)l*DIN*DST,
                                                  ssm_D + (size_t)l*DIN, l);
            ssm_xup_kernel<<<dim3(2, BSZ), 256>>>(ssm_wout + (size_t)l*DIN*DM, k, l);
        }
    }

    // ---- Phase B ----
    build_uniq_kernel<<<UPAD, 128>>>();
    ln_kernel<<<UPAD, 256>>>(pU, DM, pUN, DM, ln1_g, ln1_b);
    launch_tgemm<0,false,false,false,false,false>(dim3(1536/128, UPAD/128),
        pUN, DM, pWqkvR, 1536, pQKVU, 1536, nullptr, DM);

    build_x_kernel<<<NROWS, 128>>>();
    attn_full_kernel<<<dim3(NWIN, NH), 256>>>(pQKVU, pO);
    launch_tgemm<0,true,false,false,false,false>(dim3(DM/128, NROWS/128),
        pO, DM, pWoR, DM, pX, DM, nullptr, DM);
    ln_kernel<<<NROWS, 256>>>(pX, DM, pXN, DM, ln2_g, ln2_b);
    launch_tgemm<1,false,true,false,false,true>(dim3(DFFN/128, NROWS/128),
        pXN, DM, pW1R, DFFN, pW, DFFN, b1, DM);
    launch_tgemm<0,true,true,false,false,false>(dim3(DM/128, NROWS/128),
        pW, DFFN, pW2R, DM, pX, DM, b2, DFFN);

    // layer 1 (K/V at all positions, everything else only last token)
    const float* wqkv1r = pWqkvR + (size_t)1*DM*1536;
    ln_kernel<<<NROWS, 256>>>(pX, DM, pXN, DM, ln1_g + DM, ln1_b + DM);
    launch_tgemm<0,false,false,false,false,false>(dim3(1024/128, NROWS/128),
        pXN, DM, wqkv1r + 512, 1536, pW, 1024, nullptr, DM);               // KV
    launch_tgemm<0,false,false,false,false,false>(dim3(DM/128, NWIN/128),
        pXN + (size_t)64*DM, (long long)TW*DM, wqkv1r, 1536, pQl, DM, nullptr, DM); // Q
    attn_last_kernel<<<dim3(NWIN, NH), 128>>>(pQl, pW, pOl);
    launch_tgemm<0,true,false,false,false,false>(dim3(DM/128, NWIN/128),
        pOl, DM, pWoR + (size_t)DM*DM, DM, pX + (size_t)64*DM, (long long)TW*DM,
        nullptr, DM);
    ln_kernel<<<NWIN, 256>>>(pX + (size_t)64*DM, (long long)TW*DM, pXL, DM,
                             ln2_g + DM, ln2_b + DM);
    launch_tgemm<1,false,true,false,false,true>(dim3(DFFN/128, NWIN/128),
        pXL, DM, pW1R + (size_t)DM*DFFN, DFFN, pHL, DFFN, b1 + DFFN, DM);
    launch_tgemm<0,true,true,false,false,false>(dim3(DM/128, NWIN/128),
        pHL, DFFN, pW2R + (size_t)DFFN*DM, DM, pX + (size_t)64*DM, (long long)TW*DM,
        b2 + DM, DFFN);

    // final LN (last rows) + tied logits (NT, swapped grid)
    ln_kernel<<<NWIN, 256>>>(pX + (size_t)64*DM, (long long)TW*DM, pFL, DM,
                             lnf_g, lnf_b);
    launch_tgemm<0,false,false,true,true,false>(dim3(NWIN/128, VOC/128),
        pFL, DM, pEmbR, DM, out, VOC, nullptr, DM);
}